// round 10
// baseline (speedup 1.0000x reference)
#include <cuda_runtime.h>
#include <cuda_fp16.h>
#include <math.h>
#include <float.h>
#include <stdint.h>

#define TT 2048
#define HIDDEN 2048
#define NH 32
#define NKV 4
#define HD 128
#define QS (NH*HD)        // 4096
#define KVS (NKV*HD)      // 512
#define QKVN (QS + 2*KVS) // 5120

// ---------------- scratch (static device globals; no allocs) ----------------
__device__ __half g_q   [(size_t)NH * TT * HD];   //  16 MB [h][t][d]  (pre-scaled by d^-1/2 * log2e)
__device__ __half g_k   [(size_t)NKV * TT * HD];  //   2 MB [kv][t][d]
__device__ __half g_vt  [(size_t)NKV * HD * TT];  //   2 MB [kv][d][t]
__device__ __half g_attn[(size_t)TT * QS];        //  16 MB [t][h*128+d]
__device__ __half g_hidh [(size_t)TT * HIDDEN];   //   8 MB fp16(hidden)
__device__ __half g_wqkvh[(size_t)QKVN * HIDDEN]; //  20 MB fp16(w_qkv)
__device__ __half g_woh  [(size_t)HIDDEN * QS];   //  16 MB fp16(w_o)
__device__ float  g_op  [2 * (size_t)TT * HIDDEN];//  32 MB split-K partials for O-proj
__device__ float  g_invf[64];

#define ATT_SCALE 0.08838834764831845f
#define LOG2E 1.4426950408889634f
#define EXP_SHIFT_L2 5.7707801635558535f   // 4 * log2(e)

// ---------------- helpers ----------------
__device__ __forceinline__ uint32_t smem_u32(const void* p) {
    uint32_t a;
    asm("{ .reg .u64 t; cvta.to.shared.u64 t, %1; cvt.u32.u64 %0, t; }" : "=r"(a) : "l"(p));
    return a;
}
__device__ __forceinline__ void cp16(uint32_t dst, const void* src) {
    asm volatile("cp.async.cg.shared.global [%0], [%1], 16;" :: "r"(dst), "l"(src));
}
__device__ __forceinline__ void mma_f16(float* d, const unsigned* a, const unsigned* b) {
    asm volatile(
        "mma.sync.aligned.m16n8k16.row.col.f32.f16.f16.f32 "
        "{%0,%1,%2,%3}, {%4,%5,%6,%7}, {%8,%9}, {%0,%1,%2,%3};\n"
        : "+f"(d[0]), "+f"(d[1]), "+f"(d[2]), "+f"(d[3])
        : "r"(a[0]), "r"(a[1]), "r"(a[2]), "r"(a[3]), "r"(b[0]), "r"(b[1]));
}
__device__ __forceinline__ void ldsm4(unsigned* r, uint32_t addr) {
    asm volatile("ldmatrix.sync.aligned.m8n8.x4.shared.b16 {%0,%1,%2,%3}, [%4];"
        : "=r"(r[0]), "=r"(r[1]), "=r"(r[2]), "=r"(r[3]) : "r"(addr));
}
__device__ __forceinline__ float ex2f(float x) {
    float y;
    asm("ex2.approx.f32 %0, %1;" : "=f"(y) : "f"(x));
    return y;
}

// ================= dense fp16 TN GEMM (QKV fused-epilogue + O-proj split-K) =================
#define STAGES 3
#define TILE_BYTES 16384
#define STAGE_BYTES 32768
#define SM_TOT (STAGES*STAGE_BYTES + 512)
#define BM 128
#define BN 128

// mode 0: plain fp32 C out (supports split-K via blockIdx.z: A/B shifted koff_z, C shifted c_zoff)
// mode 1: fused QKV epilogue: bn = head (0-31 q, 32-35 k, 36-39 v)
__global__ __launch_bounds__(256, 2) void gemm_h(
    const __half* __restrict__ A, const __half* __restrict__ B, float* __restrict__ C,
    int K, int lda, int ldb, int ldc, float scale,
    const int* __restrict__ positions, const float* __restrict__ qw,
    const float* __restrict__ kw, int mode,
    int koff_z, long long c_zoff)
{
    int bm = blockIdx.y, bn = blockIdx.x;

    A += (long long)blockIdx.z * koff_z;
    B += (long long)blockIdx.z * koff_z;
    C += (long long)blockIdx.z * c_zoff;

    extern __shared__ char smem[];
    uint32_t sbase = smem_u32(smem);

    int tid  = threadIdx.x;
    int warp = tid >> 5, lane = tid & 31;
    int wm = warp & 3, wn = warp >> 2;
    int r = lane >> 2, c = lane & 3;

    // ldmatrix lane geometry
    int arow_in = ((lane >> 3) & 1) * 8 + (lane & 7);
    int ahi = lane >> 4;
    int am7 = lane & 7;
    int bro = ((lane >> 4) << 3) + (lane & 7);
    int bcb = (lane >> 3) & 1;
    int bb7 = lane & 7;

    float acc[2][8][4];
#pragma unroll
    for (int i = 0; i < 2; i++)
#pragma unroll
        for (int j = 0; j < 8; j++)
#pragma unroll
            for (int k = 0; k < 4; k++) acc[i][j][k] = 0.f;

    int nkt = K >> 6;
    const __half* Ab = A + (long long)bm * BM * lda;
    const __half* Bb = B + (long long)bn * BN * ldb;

    int sm_ = tid >> 1;
    int scb = (tid & 1) * 4;
    long long arow = (long long)sm_ * lda;
    long long brow = (long long)sm_ * ldb;

#pragma unroll
    for (int p = 0; p < STAGES - 1; p++) {
        if (p < nkt) {
            int kb = p << 6;
            uint32_t aD = sbase + p * STAGE_BYTES + sm_ * 128;
            uint32_t bD = aD + TILE_BYTES;
            const __half* as = Ab + arow + kb + scb * 8;
            const __half* bs = Bb + brow + kb + scb * 8;
#pragma unroll
            for (int j = 0; j < 4; j++) {
                int sw = ((scb + j) ^ (sm_ & 7)) * 16;
                cp16(aD + sw, as + j * 8);
                cp16(bD + sw, bs + j * 8);
            }
        }
        asm volatile("cp.async.commit_group;" ::: "memory");
    }

    for (int kt = 0; kt < nkt; kt++) {
        asm volatile("cp.async.wait_group 1;" ::: "memory");
        __syncthreads();

        if (kt + STAGES - 1 < nkt) {
            int kn = kt + STAGES - 1;
            int kb = kn << 6;
            uint32_t aD = sbase + (kn % STAGES) * STAGE_BYTES + sm_ * 128;
            uint32_t bD = aD + TILE_BYTES;
            const __half* as = Ab + arow + kb + scb * 8;
            const __half* bs = Bb + brow + kb + scb * 8;
#pragma unroll
            for (int j = 0; j < 4; j++) {
                int sw = ((scb + j) ^ (sm_ & 7)) * 16;
                cp16(aD + sw, as + j * 8);
                cp16(bD + sw, bs + j * 8);
            }
        }
        asm volatile("cp.async.commit_group;" ::: "memory");

        uint32_t sa  = sbase + (kt % STAGES) * STAGE_BYTES;
        uint32_t sbm = sa + TILE_BYTES;

#pragma unroll
        for (int ks = 0; ks < 4; ks++) {
            unsigned a[2][4];
#pragma unroll
            for (int mt = 0; mt < 2; mt++) {
                uint32_t row = (uint32_t)(wm * 32 + mt * 16 + arow_in);
                ldsm4(a[mt], sa + row * 128u + ((unsigned)((2 * ks + ahi) ^ am7) << 4));
            }
#pragma unroll
            for (int ntp = 0; ntp < 4; ntp++) {
                unsigned bb[4];
                uint32_t row = (uint32_t)(wn * 64 + ntp * 16 + bro);
                ldsm4(bb, sbm + row * 128u + ((unsigned)((2 * ks + bcb) ^ bb7) << 4));
#pragma unroll
                for (int mt = 0; mt < 2; mt++) {
                    mma_f16(acc[mt][2 * ntp],     a[mt], bb);
                    mma_f16(acc[mt][2 * ntp + 1], a[mt], bb + 2);
                }
            }
        }
    }

    asm volatile("cp.async.wait_group 0;" ::: "memory");

    if (mode == 0) {
#pragma unroll
        for (int mt = 0; mt < 2; mt++) {
            int m0 = bm * BM + wm * 32 + mt * 16 + r;
#pragma unroll
            for (int nt = 0; nt < 8; nt++) {
                int n0 = bn * BN + wn * 64 + nt * 8 + 2 * c;
                *(float2*)(C + (long long)m0 * ldc + n0) =
                    make_float2(acc[mt][nt][0] * scale, acc[mt][nt][1] * scale);
                *(float2*)(C + (long long)(m0 + 8) * ldc + n0) =
                    make_float2(acc[mt][nt][2] * scale, acc[mt][nt][3] * scale);
            }
        }
        return;
    }

    // ---- fused QKV epilogue ----
    __syncthreads();
    float* buf = (float*)smem;
#pragma unroll
    for (int mt = 0; mt < 2; mt++) {
        int mrow = wm * 32 + mt * 16 + r;
#pragma unroll
        for (int nt = 0; nt < 8; nt++) {
            int nc = wn * 64 + nt * 8 + 2 * c;
            *(float2*)(buf + mrow * 132 + nc)       = make_float2(acc[mt][nt][0], acc[mt][nt][1]);
            *(float2*)(buf + (mrow + 8) * 132 + nc) = make_float2(acc[mt][nt][2], acc[mt][nt][3]);
        }
    }
    __syncthreads();

    int h = bn;
    if (h < 36) {
        int row = tid >> 1, half = tid & 1;
        int t = bm * 128 + row;
        const float* own = buf + row * 132 + half * 64;
        const float* par = buf + row * 132 + (half ^ 1) * 64;

        float ss = 0.f;
#pragma unroll
        for (int i = 0; i < 16; i++) {
            float4 v = *(const float4*)(own + i * 4);
            ss += v.x * v.x + v.y * v.y + v.z * v.z + v.w * v.w;
        }
        ss += __shfl_xor_sync(0xffffffffu, ss, 1);
        float rinv = rsqrtf(ss * (1.f / 128.f) + 1e-6f);

        const float* w_ = (h < 32) ? qw : kw;
        float pos = (float)positions[t];
        float osc = (h < 32) ? (ATT_SCALE * LOG2E) : 1.f;
        float sgn = half ? 1.f : -1.f;
        __half* outp;
        if (h < 32) outp = g_q + ((size_t)h * TT + t) * HD + half * 64;
        else        outp = g_k + ((size_t)(h - 32) * TT + t) * HD + half * 64;

#pragma unroll 8
        for (int i = 0; i < 64; i += 2) {
            float cs0 = 0.f, sn0 = 0.f, cs1 = 0.f, sn1 = 0.f;
            if (!(lane & 1)) {
                float a0 = pos * g_invf[i], a1 = pos * g_invf[i + 1];
                cs0 = cosf(a0); sn0 = sinf(a0);
                cs1 = cosf(a1); sn1 = sinf(a1);
            }
            cs0 = __shfl_sync(0xffffffffu, cs0, lane & ~1);
            sn0 = __shfl_sync(0xffffffffu, sn0, lane & ~1);
            cs1 = __shfl_sync(0xffffffffu, cs1, lane & ~1);
            sn1 = __shfl_sync(0xffffffffu, sn1, lane & ~1);
            float y0 = own[i]     * rinv * w_[half * 64 + i];
            float y1 = own[i + 1] * rinv * w_[half * 64 + i + 1];
            float z0 = par[i]     * rinv * w_[(half ^ 1) * 64 + i];
            float z1 = par[i + 1] * rinv * w_[(half ^ 1) * 64 + i + 1];
            float o0 = (y0 * cs0 + sgn * z0 * sn0) * osc;
            float o1 = (y1 * cs1 + sgn * z1 * sn1) * osc;
            *(__half2*)(outp + i) = __floats2half2_rn(o0, o1);
        }
    } else {
        int d = tid >> 1, thalf = tid & 1;
        int kvh = h - 36;
        __half* vp = g_vt + ((size_t)kvh * HD + d) * TT + (size_t)bm * 128 + thalf * 64;
#pragma unroll 8
        for (int j2 = 0; j2 < 64; j2 += 2) {
            float v0 = buf[(thalf * 64 + j2) * 132 + d];
            float v1 = buf[(thalf * 64 + j2 + 1) * 132 + d];
            *(__half2*)(vp + j2) = __floats2half2_rn(v0, v1);
        }
    }
}

// ---------------- split-K combine: out = p0 + p1 ----------------
__global__ void combine_out(const float4* __restrict__ p, float4* __restrict__ out, int n4) {
    int i = blockIdx.x * 256 + threadIdx.x;
    int stride = gridDim.x * 256;
    for (; i < n4; i += stride) {
        float4 a = p[i];
        float4 b = p[i + n4];
        out[i] = make_float4(a.x + b.x, a.y + b.y, a.z + b.z, a.w + b.w);
    }
}

// ================= fused flash attention (ldmatrix fragment loads) =================
#define FSM_Q 0
#define FSM_K 32768
#define FSM_V (32768 + 65536)
#define FSM_L (FSM_V + 65536)
#define FSM_TOT (FSM_L + 1024 + 128)

__device__ __forceinline__ void flash_load_tile128(
    uint32_t sdst, const __half* src, int ld, int tid)
{
#pragma unroll
    for (int i = 0; i < 4; i++) {
        int li = tid + 512 * i;
        int row = li >> 4, cc = li & 15;
        uint32_t dst = sdst + (cc >> 3) * 16384 + row * 128 + (((cc & 7) ^ (row & 7)) * 16);
        cp16(dst, src + (long long)row * ld + cc * 8);
    }
}

__global__ __launch_bounds__(512, 1) void flash_kernel()
{
    int b = blockIdx.x;
    int bm = 15 - (b >> 5);     // heavy blocks first
    int h  = b & 31;
    int kvh = h >> 3;

    extern __shared__ char sm[];
    uint32_t sbase = smem_u32(sm);
    float* lsum = (float*)(sm + FSM_L);

    int tid = threadIdx.x;
    int w = tid >> 5, lane = tid & 31;
    int wm = w & 7, wn = w >> 3;
    int r = lane >> 2, c = lane & 3;

    int am  = wm * 16 + ((lane >> 3) & 1) * 8 + (lane & 7);
    int am7 = am & 7;
    int ahi = lane >> 4;
    uint32_t aoff = (uint32_t)am * 128u;
    int bro = ((lane >> 4) << 3) + (lane & 7);
    int bcb = (lane >> 3) & 1;
    int bb7 = bro & 7;

    const __half* qsrc = g_q + ((size_t)h * TT + (size_t)bm * 128) * HD;
    const __half* ksrc = g_k + (size_t)kvh * TT * HD;
    const __half* vsrc = g_vt + (size_t)kvh * HD * TT;

    flash_load_tile128(sbase + FSM_Q, qsrc, HD, tid);
    flash_load_tile128(sbase + FSM_K, ksrc, HD, tid);
#pragma unroll
    for (int i = 0; i < 4; i++) {
        int li = tid + 512 * i;
        int row = li >> 4, cc = li & 15;
        uint32_t dst = sbase + FSM_V + (cc >> 3) * 16384 + row * 128 + (((cc & 7) ^ (row & 7)) * 16);
        cp16(dst, vsrc + (size_t)row * TT + cc * 8);
    }
    asm volatile("cp.async.commit_group;" ::: "memory");

    float acc_o[16][4];
#pragma unroll
    for (int i = 0; i < 16; i++)
#pragma unroll
        for (int k = 0; k < 4; k++) acc_o[i][k] = 0.f;
    float l0 = 0.f, l1 = 0.f;

    int mrow0 = wm * 16 + r;

    for (int j = 0; j <= bm; j++) {
        int st = j & 1;
        asm volatile("cp.async.wait_group 0;" ::: "memory");
        __syncthreads();

        if (j < bm) {
            int jn = j + 1;
            flash_load_tile128(sbase + FSM_K + (st ^ 1) * 32768,
                               ksrc + (size_t)jn * 128 * HD, HD, tid);
#pragma unroll
            for (int i = 0; i < 4; i++) {
                int li = tid + 512 * i;
                int row = li >> 4, cc = li & 15;
                uint32_t dst = sbase + FSM_V + (st ^ 1) * 32768 + (cc >> 3) * 16384
                             + row * 128 + (((cc & 7) ^ (row & 7)) * 16);
                cp16(dst, vsrc + (size_t)row * TT + jn * 128 + cc * 8);
            }
        }
        asm volatile("cp.async.commit_group;" ::: "memory");

        // ---- S = Q @ K^T (Q pre-scaled by d^-1/2 * log2e) ----
        float acc_s[8][4];
#pragma unroll
        for (int i = 0; i < 8; i++)
#pragma unroll
            for (int k = 0; k < 4; k++) acc_s[i][k] = 0.f;

        uint32_t squ = sbase + FSM_Q;
        uint32_t sku = sbase + FSM_K + st * 32768;
#pragma unroll
        for (int kt = 0; kt < 2; kt++) {
#pragma unroll
            for (int ks = 0; ks < 4; ks++) {
                unsigned a[4];
                ldsm4(a, squ + kt * 16384 + aoff + ((unsigned)((2 * ks + ahi) ^ am7) << 4));
#pragma unroll
                for (int ntp = 0; ntp < 4; ntp++) {
                    unsigned bb[4];
                    ldsm4(bb, sku + kt * 16384 + (unsigned)(wn * 64 + ntp * 16 + bro) * 128
                              + ((unsigned)((2 * ks + bcb) ^ bb7) << 4));
                    mma_f16(acc_s[2 * ntp],     a, bb);
                    mma_f16(acc_s[2 * ntp + 1], a, bb + 2);
                }
            }
        }

        // ---- exp2 + causal mask + pack + rowsums ----
        unsigned p[16];
        bool diag = (j == bm);
#pragma unroll
        for (int nt = 0; nt < 8; nt++) {
            int n0 = wn * 64 + nt * 8 + 2 * c;
            float v0 = ex2f(acc_s[nt][0] - EXP_SHIFT_L2);
            float v1 = ex2f(acc_s[nt][1] - EXP_SHIFT_L2);
            float v2 = ex2f(acc_s[nt][2] - EXP_SHIFT_L2);
            float v3 = ex2f(acc_s[nt][3] - EXP_SHIFT_L2);
            if (diag) {
                if (n0     > mrow0)     v0 = 0.f;
                if (n0 + 1 > mrow0)     v1 = 0.f;
                if (n0     > mrow0 + 8) v2 = 0.f;
                if (n0 + 1 > mrow0 + 8) v3 = 0.f;
            }
            l0 += v0 + v1;
            l1 += v2 + v3;
            __half2 h01 = __floats2half2_rn(v0, v1);
            __half2 h23 = __floats2half2_rn(v2, v3);
            p[2 * nt]     = *(unsigned*)&h01;
            p[2 * nt + 1] = *(unsigned*)&h23;
        }

        // ---- O += P @ V ----
        uint32_t svu = sbase + FSM_V + st * 32768 + wn * 16384;
#pragma unroll
        for (int ks = 0; ks < 4; ks++) {
            unsigned a[4] = {p[4 * ks], p[4 * ks + 1], p[4 * ks + 2], p[4 * ks + 3]};
#pragma unroll
            for (int dnp = 0; dnp < 8; dnp++) {
                unsigned bb[4];
                ldsm4(bb, svu + (unsigned)(dnp * 16 + bro) * 128
                          + ((unsigned)((2 * ks + bcb) ^ bb7) << 4));
                mma_f16(acc_o[2 * dnp],     a, bb);
                mma_f16(acc_o[2 * dnp + 1], a, bb + 2);
            }
        }
    }

    // ---- cross-slice reduction + normalize + write ----
    __syncthreads();
    float* red = (float*)(sm + FSM_K);

    if (wn == 1) {
        float* dst = red + wm * 2048;
#pragma unroll
        for (int dn = 0; dn < 16; dn++) {
            *(float2*)(dst + r * 128 + dn * 8 + 2 * c)       = make_float2(acc_o[dn][0], acc_o[dn][1]);
            *(float2*)(dst + (r + 8) * 128 + dn * 8 + 2 * c) = make_float2(acc_o[dn][2], acc_o[dn][3]);
        }
    }
    l0 += __shfl_xor_sync(0xffffffffu, l0, 1);
    l0 += __shfl_xor_sync(0xffffffffu, l0, 2);
    l1 += __shfl_xor_sync(0xffffffffu, l1, 1);
    l1 += __shfl_xor_sync(0xffffffffu, l1, 2);
    if (c == 0) {
        lsum[wn * 128 + wm * 16 + r]     = l0;
        lsum[wn * 128 + wm * 16 + r + 8] = l1;
    }
    __syncthreads();

    if (wn == 0) {
        int row0 = wm * 16 + r;
        float inv0 = 1.f / (lsum[row0]     + lsum[128 + row0]);
        float inv1 = 1.f / (lsum[row0 + 8] + lsum[128 + row0 + 8]);
        const float* src = red + wm * 2048;
        __half* o0 = g_attn + (size_t)(bm * 128 + row0) * QS + h * 128;
        __half* o1 = g_attn + (size_t)(bm * 128 + row0 + 8) * QS + h * 128;
#pragma unroll
        for (int dn = 0; dn < 16; dn++) {
            int nc = dn * 8 + 2 * c;
            float2 s0 = *(const float2*)(src + r * 128 + nc);
            float2 s1 = *(const float2*)(src + (r + 8) * 128 + nc);
            *(__half2*)(o0 + nc) = __floats2half2_rn((acc_o[dn][0] + s0.x) * inv0,
                                                     (acc_o[dn][1] + s0.y) * inv0);
            *(__half2*)(o1 + nc) = __floats2half2_rn((acc_o[dn][2] + s1.x) * inv1,
                                                     (acc_o[dn][3] + s1.y) * inv1);
        }
    }
}

// ---------------- fp32 -> fp16 conversion (all three arrays, one launch) ----------------
#define N4_HID  (TT * HIDDEN / 4)
#define N4_WQKV (QKVN * HIDDEN / 4)
#define N4_WO   (HIDDEN * QS / 4)
__global__ void h_conv_all(const float4* __restrict__ s0, uint2* __restrict__ d0,
                           const float4* __restrict__ s1, uint2* __restrict__ d1,
                           const float4* __restrict__ s2, uint2* __restrict__ d2) {
    int i = blockIdx.x * 256 + threadIdx.x;
    int stride = gridDim.x * 256;
    int ntot = N4_HID + N4_WQKV + N4_WO;
    for (; i < ntot; i += stride) {
        const float4* s; uint2* d; int idx;
        if (i < N4_HID)              { s = s0; d = d0; idx = i; }
        else if (i < N4_HID + N4_WQKV) { s = s1; d = d1; idx = i - N4_HID; }
        else                         { s = s2; d = d2; idx = i - N4_HID - N4_WQKV; }
        float4 v = s[idx];
        __half2 lo = __floats2half2_rn(v.x, v.y);
        __half2 hi = __floats2half2_rn(v.z, v.w);
        uint2 o;
        o.x = *(unsigned*)&lo;
        o.y = *(unsigned*)&hi;
        d[idx] = o;
    }
}

// ---------------- inv_freq ----------------
__global__ void init_invf() {
    int i = threadIdx.x;
    if (i < 64)
        g_invf[i] = (float)exp(-(double)i * (log(10000.0) / 64.0));
}

// ---------------- launcher ----------------
extern "C" void kernel_launch(void* const* d_in, const int* in_sizes, int n_in,
                              void* d_out, int out_size)
{
    const int* positions = (const int*)d_in[0];   // int32 (JAX x64 disabled)
    const float* hidden = (const float*)d_in[1];
    const float* w_qkv  = (const float*)d_in[2];
    const float* w_o    = (const float*)d_in[3];
    const float* qw     = (const float*)d_in[4];
    const float* kw     = (const float*)d_in[5];
    float* out = (float*)d_out;

    __half *p_attn, *p_hidh, *p_wqkvh, *p_woh;
    float *p_op;
    cudaGetSymbolAddress((void**)&p_attn,  g_attn);
    cudaGetSymbolAddress((void**)&p_hidh,  g_hidh);
    cudaGetSymbolAddress((void**)&p_wqkvh, g_wqkvh);
    cudaGetSymbolAddress((void**)&p_woh,   g_woh);
    cudaGetSymbolAddress((void**)&p_op,    g_op);

    cudaFuncSetAttribute(gemm_h, cudaFuncAttributeMaxDynamicSharedMemorySize, SM_TOT);
    cudaFuncSetAttribute(flash_kernel, cudaFuncAttributeMaxDynamicSharedMemorySize, FSM_TOT);

    init_invf<<<1, 64>>>();

    // 0) fp16 conversions (one launch)
    h_conv_all<<<2048, 256>>>((const float4*)hidden, (uint2*)p_hidh,
                              (const float4*)w_qkv,  (uint2*)p_wqkvh,
                              (const float4*)w_o,    (uint2*)p_woh);

    // 1) QKV projection with fused RMSNorm+RoPE+reorder epilogue
    gemm_h<<<dim3(QKVN / BN, TT / BM, 1), 256, SM_TOT>>>(
        p_hidh, p_wqkvh, nullptr, HIDDEN, HIDDEN, HIDDEN, 0, 1.0f,
        positions, qw, kw, 1, 0, 0);

    // 2) fused flash attention -> g_attn (fp16)
    flash_kernel<<<512, 512, FSM_TOT>>>();

    // 3) output projection, split-K x2 (fp32 partials)
    gemm_h<<<dim3(HIDDEN / BN, TT / BM, 2), 256, SM_TOT>>>(
        p_attn, p_woh, p_op, QS / 2, QS, QS, HIDDEN, 1.0f,
        nullptr, nullptr, nullptr, 0, QS / 2, (long long)TT * HIDDEN);

    // 4) combine partials -> out
    combine_out<<<1024, 256>>>((const float4*)p_op, (float4*)out, TT * HIDDEN / 4);
}

// round 11
// speedup vs baseline: 1.0179x; 1.0179x over previous
#include <cuda_runtime.h>
#include <cuda_fp16.h>
#include <math.h>
#include <float.h>
#include <stdint.h>

#define TT 2048
#define HIDDEN 2048
#define NH 32
#define NKV 4
#define HD 128
#define QS (NH*HD)        // 4096
#define KVS (NKV*HD)      // 512
#define QKVN (QS + 2*KVS) // 5120

// ---------------- scratch (static device globals; no allocs) ----------------
__device__ __half g_q   [(size_t)NH * TT * HD];   //  16 MB [h][t][d]  (pre-scaled by d^-1/2 * log2e)
__device__ __half g_k   [(size_t)NKV * TT * HD];  //   2 MB [kv][t][d]
__device__ __half g_vt  [(size_t)NKV * HD * TT];  //   2 MB [kv][d][t]
__device__ __half g_attn[(size_t)TT * QS];        //  16 MB [t][h*128+d]
__device__ __half g_hidh [(size_t)TT * HIDDEN];   //   8 MB fp16(hidden)
__device__ __half g_wqkvh[(size_t)QKVN * HIDDEN]; //  20 MB fp16(w_qkv)
__device__ __half g_woh  [(size_t)HIDDEN * QS];   //  16 MB fp16(w_o)
__device__ float  g_invf[64];

#define ATT_SCALE 0.08838834764831845f
#define LOG2E 1.4426950408889634f
#define EXP_SHIFT_L2 5.7707801635558535f   // 4 * log2(e)

// ---------------- helpers ----------------
__device__ __forceinline__ uint32_t smem_u32(const void* p) {
    uint32_t a;
    asm("{ .reg .u64 t; cvta.to.shared.u64 t, %1; cvt.u32.u64 %0, t; }" : "=r"(a) : "l"(p));
    return a;
}
__device__ __forceinline__ void cp16(uint32_t dst, const void* src) {
    asm volatile("cp.async.cg.shared.global [%0], [%1], 16;" :: "r"(dst), "l"(src));
}
__device__ __forceinline__ void mma_f16(float* d, const unsigned* a, const unsigned* b) {
    asm volatile(
        "mma.sync.aligned.m16n8k16.row.col.f32.f16.f16.f32 "
        "{%0,%1,%2,%3}, {%4,%5,%6,%7}, {%8,%9}, {%0,%1,%2,%3};\n"
        : "+f"(d[0]), "+f"(d[1]), "+f"(d[2]), "+f"(d[3])
        : "r"(a[0]), "r"(a[1]), "r"(a[2]), "r"(a[3]), "r"(b[0]), "r"(b[1]));
}
__device__ __forceinline__ void ldsm4(unsigned* r, uint32_t addr) {
    asm volatile("ldmatrix.sync.aligned.m8n8.x4.shared.b16 {%0,%1,%2,%3}, [%4];"
        : "=r"(r[0]), "=r"(r[1]), "=r"(r[2]), "=r"(r[3]) : "r"(addr));
}
__device__ __forceinline__ float ex2f(float x) {
    float y;
    asm("ex2.approx.f32 %0, %1;" : "=f"(y) : "f"(x));
    return y;
}

// ================= dense fp16 TN GEMM (QKV fused-epilogue + O-proj) =================
#define STAGES 3
#define TILE_BYTES 16384
#define STAGE_BYTES 32768
#define SM_TOT (STAGES*STAGE_BYTES + 512)
#define BM 128
#define BN 128

// mode 0: plain fp32 C out
// mode 1: fused QKV epilogue: bn = head (0-31 q, 32-35 k, 36-39 v)
__global__ __launch_bounds__(256, 2) void gemm_h(
    const __half* __restrict__ A, const __half* __restrict__ B, float* __restrict__ C,
    int K, int lda, int ldb, int ldc, float scale,
    const int* __restrict__ positions, const float* __restrict__ qw,
    const float* __restrict__ kw, int mode)
{
    int bm = blockIdx.y, bn = blockIdx.x;

    extern __shared__ char smem[];
    uint32_t sbase = smem_u32(smem);

    int tid  = threadIdx.x;
    int warp = tid >> 5, lane = tid & 31;
    int wm = warp & 3, wn = warp >> 2;
    int r = lane >> 2, c = lane & 3;

    // ldmatrix lane geometry
    int arow_in = ((lane >> 3) & 1) * 8 + (lane & 7);
    int ahi = lane >> 4;
    int am7 = lane & 7;
    int bro = ((lane >> 4) << 3) + (lane & 7);
    int bcb = (lane >> 3) & 1;
    int bb7 = lane & 7;

    float acc[2][8][4];
#pragma unroll
    for (int i = 0; i < 2; i++)
#pragma unroll
        for (int j = 0; j < 8; j++)
#pragma unroll
            for (int k = 0; k < 4; k++) acc[i][j][k] = 0.f;

    int nkt = K >> 6;
    const __half* Ab = A + (long long)bm * BM * lda;
    const __half* Bb = B + (long long)bn * BN * ldb;

    int sm_ = tid >> 1;
    int scb = (tid & 1) * 4;
    long long arow = (long long)sm_ * lda;
    long long brow = (long long)sm_ * ldb;

#pragma unroll
    for (int p = 0; p < STAGES - 1; p++) {
        if (p < nkt) {
            int kb = p << 6;
            uint32_t aD = sbase + p * STAGE_BYTES + sm_ * 128;
            uint32_t bD = aD + TILE_BYTES;
            const __half* as = Ab + arow + kb + scb * 8;
            const __half* bs = Bb + brow + kb + scb * 8;
#pragma unroll
            for (int j = 0; j < 4; j++) {
                int sw = ((scb + j) ^ (sm_ & 7)) * 16;
                cp16(aD + sw, as + j * 8);
                cp16(bD + sw, bs + j * 8);
            }
        }
        asm volatile("cp.async.commit_group;" ::: "memory");
    }

    for (int kt = 0; kt < nkt; kt++) {
        asm volatile("cp.async.wait_group 1;" ::: "memory");
        __syncthreads();

        if (kt + STAGES - 1 < nkt) {
            int kn = kt + STAGES - 1;
            int kb = kn << 6;
            uint32_t aD = sbase + (kn % STAGES) * STAGE_BYTES + sm_ * 128;
            uint32_t bD = aD + TILE_BYTES;
            const __half* as = Ab + arow + kb + scb * 8;
            const __half* bs = Bb + brow + kb + scb * 8;
#pragma unroll
            for (int j = 0; j < 4; j++) {
                int sw = ((scb + j) ^ (sm_ & 7)) * 16;
                cp16(aD + sw, as + j * 8);
                cp16(bD + sw, bs + j * 8);
            }
        }
        asm volatile("cp.async.commit_group;" ::: "memory");

        uint32_t sa  = sbase + (kt % STAGES) * STAGE_BYTES;
        uint32_t sbm = sa + TILE_BYTES;

#pragma unroll
        for (int ks = 0; ks < 4; ks++) {
            unsigned a[2][4];
#pragma unroll
            for (int mt = 0; mt < 2; mt++) {
                uint32_t row = (uint32_t)(wm * 32 + mt * 16 + arow_in);
                ldsm4(a[mt], sa + row * 128u + ((unsigned)((2 * ks + ahi) ^ am7) << 4));
            }
#pragma unroll
            for (int ntp = 0; ntp < 4; ntp++) {
                unsigned bb[4];
                uint32_t row = (uint32_t)(wn * 64 + ntp * 16 + bro);
                ldsm4(bb, sbm + row * 128u + ((unsigned)((2 * ks + bcb) ^ bb7) << 4));
#pragma unroll
                for (int mt = 0; mt < 2; mt++) {
                    mma_f16(acc[mt][2 * ntp],     a[mt], bb);
                    mma_f16(acc[mt][2 * ntp + 1], a[mt], bb + 2);
                }
            }
        }
    }

    asm volatile("cp.async.wait_group 0;" ::: "memory");

    if (mode == 0) {
#pragma unroll
        for (int mt = 0; mt < 2; mt++) {
            int m0 = bm * BM + wm * 32 + mt * 16 + r;
#pragma unroll
            for (int nt = 0; nt < 8; nt++) {
                int n0 = bn * BN + wn * 64 + nt * 8 + 2 * c;
                *(float2*)(C + (long long)m0 * ldc + n0) =
                    make_float2(acc[mt][nt][0] * scale, acc[mt][nt][1] * scale);
                *(float2*)(C + (long long)(m0 + 8) * ldc + n0) =
                    make_float2(acc[mt][nt][2] * scale, acc[mt][nt][3] * scale);
            }
        }
        return;
    }

    // ---- fused QKV epilogue ----
    __syncthreads();
    float* buf = (float*)smem;
#pragma unroll
    for (int mt = 0; mt < 2; mt++) {
        int mrow = wm * 32 + mt * 16 + r;
#pragma unroll
        for (int nt = 0; nt < 8; nt++) {
            int nc = wn * 64 + nt * 8 + 2 * c;
            *(float2*)(buf + mrow * 132 + nc)       = make_float2(acc[mt][nt][0], acc[mt][nt][1]);
            *(float2*)(buf + (mrow + 8) * 132 + nc) = make_float2(acc[mt][nt][2], acc[mt][nt][3]);
        }
    }
    __syncthreads();

    int h = bn;
    if (h < 36) {
        int row = tid >> 1, half = tid & 1;
        int t = bm * 128 + row;
        const float* own = buf + row * 132 + half * 64;
        const float* par = buf + row * 132 + (half ^ 1) * 64;

        float ss = 0.f;
#pragma unroll
        for (int i = 0; i < 16; i++) {
            float4 v = *(const float4*)(own + i * 4);
            ss += v.x * v.x + v.y * v.y + v.z * v.z + v.w * v.w;
        }
        ss += __shfl_xor_sync(0xffffffffu, ss, 1);
        float rinv = rsqrtf(ss * (1.f / 128.f) + 1e-6f);

        const float* w_ = (h < 32) ? qw : kw;
        float pos = (float)positions[t];
        float osc = (h < 32) ? (ATT_SCALE * LOG2E) : 1.f;
        float sgn = half ? 1.f : -1.f;
        __half* outp;
        if (h < 32) outp = g_q + ((size_t)h * TT + t) * HD + half * 64;
        else        outp = g_k + ((size_t)(h - 32) * TT + t) * HD + half * 64;

#pragma unroll 8
        for (int i = 0; i < 64; i += 2) {
            float cs0 = 0.f, sn0 = 0.f, cs1 = 0.f, sn1 = 0.f;
            if (!(lane & 1)) {
                float a0 = pos * g_invf[i], a1 = pos * g_invf[i + 1];
                cs0 = cosf(a0); sn0 = sinf(a0);
                cs1 = cosf(a1); sn1 = sinf(a1);
            }
            cs0 = __shfl_sync(0xffffffffu, cs0, lane & ~1);
            sn0 = __shfl_sync(0xffffffffu, sn0, lane & ~1);
            cs1 = __shfl_sync(0xffffffffu, cs1, lane & ~1);
            sn1 = __shfl_sync(0xffffffffu, sn1, lane & ~1);
            float y0 = own[i]     * rinv * w_[half * 64 + i];
            float y1 = own[i + 1] * rinv * w_[half * 64 + i + 1];
            float z0 = par[i]     * rinv * w_[(half ^ 1) * 64 + i];
            float z1 = par[i + 1] * rinv * w_[(half ^ 1) * 64 + i + 1];
            float o0 = (y0 * cs0 + sgn * z0 * sn0) * osc;
            float o1 = (y1 * cs1 + sgn * z1 * sn1) * osc;
            *(__half2*)(outp + i) = __floats2half2_rn(o0, o1);
        }
    } else {
        int d = tid >> 1, thalf = tid & 1;
        int kvh = h - 36;
        __half* vp = g_vt + ((size_t)kvh * HD + d) * TT + (size_t)bm * 128 + thalf * 64;
#pragma unroll 8
        for (int j2 = 0; j2 < 64; j2 += 2) {
            float v0 = buf[(thalf * 64 + j2) * 132 + d];
            float v1 = buf[(thalf * 64 + j2 + 1) * 132 + d];
            *(__half2*)(vp + j2) = __floats2half2_rn(v0, v1);
        }
    }
}

// ================= fused flash attention (interleaved exp/PV) =================
#define FSM_Q 0
#define FSM_K 32768
#define FSM_V (32768 + 65536)
#define FSM_L (FSM_V + 65536)
#define FSM_TOT (FSM_L + 1024 + 128)

__device__ __forceinline__ void flash_load_tile128(
    uint32_t sdst, const __half* src, int ld, int tid)
{
#pragma unroll
    for (int i = 0; i < 4; i++) {
        int li = tid + 512 * i;
        int row = li >> 4, cc = li & 15;
        uint32_t dst = sdst + (cc >> 3) * 16384 + row * 128 + (((cc & 7) ^ (row & 7)) * 16);
        cp16(dst, src + (long long)row * ld + cc * 8);
    }
}

__global__ __launch_bounds__(512, 1) void flash_kernel()
{
    int b = blockIdx.x;
    int bm = 15 - (b >> 5);     // heavy blocks first
    int h  = b & 31;
    int kvh = h >> 3;

    extern __shared__ char sm[];
    uint32_t sbase = smem_u32(sm);
    float* lsum = (float*)(sm + FSM_L);

    int tid = threadIdx.x;
    int w = tid >> 5, lane = tid & 31;
    int wm = w & 7, wn = w >> 3;
    int r = lane >> 2, c = lane & 3;

    int am  = wm * 16 + ((lane >> 3) & 1) * 8 + (lane & 7);
    int am7 = am & 7;
    int ahi = lane >> 4;
    uint32_t aoff = (uint32_t)am * 128u;
    int bro = ((lane >> 4) << 3) + (lane & 7);
    int bcb = (lane >> 3) & 1;
    int bb7 = bro & 7;

    const __half* qsrc = g_q + ((size_t)h * TT + (size_t)bm * 128) * HD;
    const __half* ksrc = g_k + (size_t)kvh * TT * HD;
    const __half* vsrc = g_vt + (size_t)kvh * HD * TT;

    flash_load_tile128(sbase + FSM_Q, qsrc, HD, tid);
    flash_load_tile128(sbase + FSM_K, ksrc, HD, tid);
#pragma unroll
    for (int i = 0; i < 4; i++) {
        int li = tid + 512 * i;
        int row = li >> 4, cc = li & 15;
        uint32_t dst = sbase + FSM_V + (cc >> 3) * 16384 + row * 128 + (((cc & 7) ^ (row & 7)) * 16);
        cp16(dst, vsrc + (size_t)row * TT + cc * 8);
    }
    asm volatile("cp.async.commit_group;" ::: "memory");

    float acc_o[16][4];
#pragma unroll
    for (int i = 0; i < 16; i++)
#pragma unroll
        for (int k = 0; k < 4; k++) acc_o[i][k] = 0.f;
    float l0a = 0.f, l0b = 0.f, l1a = 0.f, l1b = 0.f;

    int mrow0 = wm * 16 + r;

    for (int j = 0; j <= bm; j++) {
        int st = j & 1;
        asm volatile("cp.async.wait_group 0;" ::: "memory");
        __syncthreads();

        if (j < bm) {
            int jn = j + 1;
            flash_load_tile128(sbase + FSM_K + (st ^ 1) * 32768,
                               ksrc + (size_t)jn * 128 * HD, HD, tid);
#pragma unroll
            for (int i = 0; i < 4; i++) {
                int li = tid + 512 * i;
                int row = li >> 4, cc = li & 15;
                uint32_t dst = sbase + FSM_V + (st ^ 1) * 32768 + (cc >> 3) * 16384
                             + row * 128 + (((cc & 7) ^ (row & 7)) * 16);
                cp16(dst, vsrc + (size_t)row * TT + jn * 128 + cc * 8);
            }
        }
        asm volatile("cp.async.commit_group;" ::: "memory");

        // ---- S = Q @ K^T (Q pre-scaled by d^-1/2 * log2e) ----
        float acc_s[8][4];
#pragma unroll
        for (int i = 0; i < 8; i++)
#pragma unroll
            for (int k = 0; k < 4; k++) acc_s[i][k] = 0.f;

        uint32_t squ = sbase + FSM_Q;
        uint32_t sku = sbase + FSM_K + st * 32768;
#pragma unroll
        for (int kt = 0; kt < 2; kt++) {
#pragma unroll
            for (int ks = 0; ks < 4; ks++) {
                unsigned a[4];
                ldsm4(a, squ + kt * 16384 + aoff + ((unsigned)((2 * ks + ahi) ^ am7) << 4));
#pragma unroll
                for (int ntp = 0; ntp < 4; ntp++) {
                    unsigned bb[4];
                    ldsm4(bb, sku + kt * 16384 + (unsigned)(wn * 64 + ntp * 16 + bro) * 128
                              + ((unsigned)((2 * ks + bcb) ^ bb7) << 4));
                    mma_f16(acc_s[2 * ntp],     a, bb);
                    mma_f16(acc_s[2 * ntp + 1], a, bb + 2);
                }
            }
        }

        // ---- interleaved exp2/mask/pack + PV mma (per ks-chunk) ----
        bool diag = (j == bm);
        uint32_t svu = sbase + FSM_V + st * 32768 + wn * 16384;
#pragma unroll
        for (int ks = 0; ks < 4; ks++) {
            unsigned a[4];
#pragma unroll
            for (int q = 0; q < 2; q++) {
                int nt = 2 * ks + q;
                int n0 = wn * 64 + nt * 8 + 2 * c;
                float v0 = ex2f(acc_s[nt][0] - EXP_SHIFT_L2);
                float v1 = ex2f(acc_s[nt][1] - EXP_SHIFT_L2);
                float v2 = ex2f(acc_s[nt][2] - EXP_SHIFT_L2);
                float v3 = ex2f(acc_s[nt][3] - EXP_SHIFT_L2);
                if (diag) {
                    if (n0     > mrow0)     v0 = 0.f;
                    if (n0 + 1 > mrow0)     v1 = 0.f;
                    if (n0     > mrow0 + 8) v2 = 0.f;
                    if (n0 + 1 > mrow0 + 8) v3 = 0.f;
                }
                if (q == 0) { l0a += v0 + v1; l1a += v2 + v3; }
                else        { l0b += v0 + v1; l1b += v2 + v3; }
                __half2 h01 = __floats2half2_rn(v0, v1);
                __half2 h23 = __floats2half2_rn(v2, v3);
                a[2 * q]     = *(unsigned*)&h01;
                a[2 * q + 1] = *(unsigned*)&h23;
            }
#pragma unroll
            for (int dnp = 0; dnp < 8; dnp++) {
                unsigned bb[4];
                ldsm4(bb, svu + (unsigned)(dnp * 16 + bro) * 128
                          + ((unsigned)((2 * ks + bcb) ^ bb7) << 4));
                mma_f16(acc_o[2 * dnp],     a, bb);
                mma_f16(acc_o[2 * dnp + 1], a, bb + 2);
            }
        }
    }

    // ---- cross-slice reduction + normalize + write ----
    __syncthreads();
    float* red = (float*)(sm + FSM_K);

    if (wn == 1) {
        float* dst = red + wm * 2048;
#pragma unroll
        for (int dn = 0; dn < 16; dn++) {
            *(float2*)(dst + r * 128 + dn * 8 + 2 * c)       = make_float2(acc_o[dn][0], acc_o[dn][1]);
            *(float2*)(dst + (r + 8) * 128 + dn * 8 + 2 * c) = make_float2(acc_o[dn][2], acc_o[dn][3]);
        }
    }
    float l0 = l0a + l0b, l1 = l1a + l1b;
    l0 += __shfl_xor_sync(0xffffffffu, l0, 1);
    l0 += __shfl_xor_sync(0xffffffffu, l0, 2);
    l1 += __shfl_xor_sync(0xffffffffu, l1, 1);
    l1 += __shfl_xor_sync(0xffffffffu, l1, 2);
    if (c == 0) {
        lsum[wn * 128 + wm * 16 + r]     = l0;
        lsum[wn * 128 + wm * 16 + r + 8] = l1;
    }
    __syncthreads();

    if (wn == 0) {
        int row0 = wm * 16 + r;
        float inv0 = 1.f / (lsum[row0]     + lsum[128 + row0]);
        float inv1 = 1.f / (lsum[row0 + 8] + lsum[128 + row0 + 8]);
        const float* src = red + wm * 2048;
        __half* o0 = g_attn + (size_t)(bm * 128 + row0) * QS + h * 128;
        __half* o1 = g_attn + (size_t)(bm * 128 + row0 + 8) * QS + h * 128;
#pragma unroll
        for (int dn = 0; dn < 16; dn++) {
            int nc = dn * 8 + 2 * c;
            float2 s0 = *(const float2*)(src + r * 128 + nc);
            float2 s1 = *(const float2*)(src + (r + 8) * 128 + nc);
            *(__half2*)(o0 + nc) = __floats2half2_rn((acc_o[dn][0] + s0.x) * inv0,
                                                     (acc_o[dn][1] + s0.y) * inv0);
            *(__half2*)(o1 + nc) = __floats2half2_rn((acc_o[dn][2] + s1.x) * inv1,
                                                     (acc_o[dn][3] + s1.y) * inv1);
        }
    }
}

// ---------------- fp32 -> fp16 conversion (all three arrays, one launch) ----------------
#define N4_HID  (TT * HIDDEN / 4)
#define N4_WQKV (QKVN * HIDDEN / 4)
#define N4_WO   (HIDDEN * QS / 4)
__global__ void h_conv_all(const float4* __restrict__ s0, uint2* __restrict__ d0,
                           const float4* __restrict__ s1, uint2* __restrict__ d1,
                           const float4* __restrict__ s2, uint2* __restrict__ d2) {
    int i = blockIdx.x * 256 + threadIdx.x;
    int stride = gridDim.x * 256;
    int ntot = N4_HID + N4_WQKV + N4_WO;
    for (; i < ntot; i += stride) {
        const float4* s; uint2* d; int idx;
        if (i < N4_HID)              { s = s0; d = d0; idx = i; }
        else if (i < N4_HID + N4_WQKV) { s = s1; d = d1; idx = i - N4_HID; }
        else                         { s = s2; d = d2; idx = i - N4_HID - N4_WQKV; }
        float4 v = s[idx];
        __half2 lo = __floats2half2_rn(v.x, v.y);
        __half2 hi = __floats2half2_rn(v.z, v.w);
        uint2 o;
        o.x = *(unsigned*)&lo;
        o.y = *(unsigned*)&hi;
        d[idx] = o;
    }
}

// ---------------- inv_freq ----------------
__global__ void init_invf() {
    int i = threadIdx.x;
    if (i < 64)
        g_invf[i] = (float)exp(-(double)i * (log(10000.0) / 64.0));
}

// ---------------- launcher ----------------
extern "C" void kernel_launch(void* const* d_in, const int* in_sizes, int n_in,
                              void* d_out, int out_size)
{
    const int* positions = (const int*)d_in[0];   // int32 (JAX x64 disabled)
    const float* hidden = (const float*)d_in[1];
    const float* w_qkv  = (const float*)d_in[2];
    const float* w_o    = (const float*)d_in[3];
    const float* qw     = (const float*)d_in[4];
    const float* kw     = (const float*)d_in[5];
    float* out = (float*)d_out;

    __half *p_attn, *p_hidh, *p_wqkvh, *p_woh;
    cudaGetSymbolAddress((void**)&p_attn,  g_attn);
    cudaGetSymbolAddress((void**)&p_hidh,  g_hidh);
    cudaGetSymbolAddress((void**)&p_wqkvh, g_wqkvh);
    cudaGetSymbolAddress((void**)&p_woh,   g_woh);

    cudaFuncSetAttribute(gemm_h, cudaFuncAttributeMaxDynamicSharedMemorySize, SM_TOT);
    cudaFuncSetAttribute(flash_kernel, cudaFuncAttributeMaxDynamicSharedMemorySize, FSM_TOT);

    init_invf<<<1, 64>>>();

    // 0) fp16 conversions (one launch)
    h_conv_all<<<2048, 256>>>((const float4*)hidden, (uint2*)p_hidh,
                              (const float4*)w_qkv,  (uint2*)p_wqkvh,
                              (const float4*)w_o,    (uint2*)p_woh);

    // 1) QKV projection with fused RMSNorm+RoPE+reorder epilogue
    gemm_h<<<dim3(QKVN / BN, TT / BM, 1), 256, SM_TOT>>>(
        p_hidh, p_wqkvh, nullptr, HIDDEN, HIDDEN, HIDDEN, 0, 1.0f,
        positions, qw, kw, 1);

    // 2) fused flash attention -> g_attn (fp16)
    flash_kernel<<<512, 512, FSM_TOT>>>();

    // 3) output projection (fp32 out, direct write — split-K reverted)
    gemm_h<<<dim3(HIDDEN / BN, TT / BM, 1), 256, SM_TOT>>>(
        p_attn, p_woh, out, QS, QS, QS, HIDDEN, 1.0f,
        nullptr, nullptr, nullptr, 0);
}